// round 6
// baseline (speedup 1.0000x reference)
#include <cuda_runtime.h>

// Problem constants
#define BB 4
#define DDIM 64
#define HW (512*512)
#define KK 32

// Tiling: each block = 4 channels (one quad) x CP pixels of one image.
#define T 256
#define CP 16384
#define NCHUNK (HW/CP)     // 16
#define PPT (CP/T)         // 64 pixels per thread
#define UB 8               // pixels per load batch
#define NB (PPT/UB)        // 8 batches
#define QG (DDIM/4)        // 16 channel quads
#define QHALF (QG/2)       // 8 quads per launch half

// Global scratch (no allocations allowed)
__device__ float g_sum[BB*KK*DDIM];   // per (b,k,d) feature sums
__device__ float g_sq[BB*KK];         // per (b,k) sum of ||f||^2
__device__ float g_cnt[BB*KK];        // per (b,k) pixel counts

__global__ void zero_kernel() {
    int t = blockIdx.x * blockDim.x + threadIdx.x;
    int n = BB*KK*DDIM;
    for (int i = t; i < n; i += gridDim.x * blockDim.x) g_sum[i] = 0.f;
    if (t < BB*KK) { g_sq[t] = 0.f; g_cnt[t] = 0.f; }
}

// SMEM layout (dynamic, 196608 B):
//   s4   : KK*T float4  per-bin per-thread 4-channel partial sums
//   s_sq : KK*T float   per-bin per-thread ||f||^2 partials (this quad)
//   s_cnt: KK*T float   per-bin per-thread counts (quad 0 only)
// Column = tid -> bank = lane: conflict-free, race-free.
__global__ __launch_bounds__(T) void accum_kernel(
    const float* __restrict__ feats, const int* __restrict__ labels,
    int b, int qoff)
{
    extern __shared__ float smem[];
    float4* s4    = (float4*)smem;          // KK*T float4
    float*  s_sq  = smem + KK*T*4;          // KK*T floats
    float*  s_cnt = s_sq + KK*T;            // KK*T floats

    const int t     = threadIdx.x;
    const int chunk = blockIdx.x;
    const int q     = qoff + blockIdx.y;    // channel quad
    const bool do_cnt = (q == 0);
    const int lane = t & 31;
    const int w    = t >> 5;

    // zero SMEM bins
    for (int i = t; i < KK*T; i += T) s4[i] = make_float4(0.f, 0.f, 0.f, 0.f);
    for (int i = t; i < KK*T; i += T) s_sq[i] = 0.f;
    if (do_cnt) for (int i = t; i < KK*T; i += T) s_cnt[i] = 0.f;
    __syncthreads();

    const size_t base = (size_t)(b*DDIM + q*4) * HW + (size_t)chunk * CP;
    const float* __restrict__ f0 = feats + base;
    const float* __restrict__ f1 = f0 + HW;
    const float* __restrict__ f2 = f1 + HW;
    const float* __restrict__ f3 = f2 + HW;
    const int*   __restrict__ lp = labels + (size_t)b * HW + (size_t)chunk * CP;

    // Double-buffered staging. All indices constant-fold after unroll ->
    // arrays stay in registers (no lambdas, no pointer params).
    float4 vbuf[2][UB];
    int    lbuf[2][UB];

    // prologue: load batch 0 into buffer 0
#pragma unroll
    for (int u = 0; u < UB; ++u) {
        const int idx = u*T + t;
        lbuf[0][u] = lp[idx] & 31;
        vbuf[0][u].x = f0[idx];
        vbuf[0][u].y = f1[idx];
        vbuf[0][u].z = f2[idx];
        vbuf[0][u].w = f3[idx];
    }

#pragma unroll
    for (int bt = 0; bt < NB; ++bt) {
        const int cur = bt & 1;
        const int nxt = cur ^ 1;
        if (bt + 1 < NB) {
#pragma unroll
            for (int u = 0; u < UB; ++u) {
                const int idx = (bt+1)*UB*T + u*T + t;
                lbuf[nxt][u] = lp[idx] & 31;
                vbuf[nxt][u].x = f0[idx];
                vbuf[nxt][u].y = f1[idx];
                vbuf[nxt][u].z = f2[idx];
                vbuf[nxt][u].w = f3[idx];
            }
        }
#pragma unroll
        for (int u = 0; u < UB; ++u) {
            const float4 v = vbuf[cur][u];
            const int col = lbuf[cur][u]*T + t;
            float4 a = s4[col];
            a.x += v.x; a.y += v.y; a.z += v.z; a.w += v.w;
            s4[col] = a;
            float ss = v.x * v.x;
            ss = fmaf(v.y, v.y, ss);
            ss = fmaf(v.z, v.z, ss);
            ss = fmaf(v.w, v.w, ss);
            s_sq[col] += ss;
            if (do_cnt) s_cnt[col] += 1.f;
        }
    }
    __syncthreads();

    // flush: warp w reduces bins 4w..4w+3 across the 256 columns
#pragma unroll
    for (int bbn = 0; bbn < 4; ++bbn) {
        const int bin = w*4 + bbn;
        float4 a = make_float4(0.f, 0.f, 0.f, 0.f);
        float sq = 0.f, cn = 0.f;
#pragma unroll
        for (int j = 0; j < T/32; ++j) {
            const int col = bin*T + j*32 + lane;
            float4 x = s4[col];
            a.x += x.x; a.y += x.y; a.z += x.z; a.w += x.w;
            sq += s_sq[col];
            if (do_cnt) cn += s_cnt[col];
        }
#pragma unroll
        for (int off = 16; off; off >>= 1) {
            a.x += __shfl_xor_sync(0xffffffffu, a.x, off);
            a.y += __shfl_xor_sync(0xffffffffu, a.y, off);
            a.z += __shfl_xor_sync(0xffffffffu, a.z, off);
            a.w += __shfl_xor_sync(0xffffffffu, a.w, off);
            sq  += __shfl_xor_sync(0xffffffffu, sq,  off);
            cn  += __shfl_xor_sync(0xffffffffu, cn,  off);
        }
        if (lane < 4) {
            float val = (lane == 0) ? a.x : (lane == 1) ? a.y : (lane == 2) ? a.z : a.w;
            atomicAdd(&g_sum[(b*KK + bin)*DDIM + q*4 + lane], val);
        }
        if (lane == 4)            atomicAdd(&g_sq[b*KK + bin], sq);
        if (do_cnt && lane == 5)  atomicAdd(&g_cnt[b*KK + bin], cn);
    }
}

__global__ void finalize_kernel(float* __restrict__ out) {
    __shared__ float s_mean[KK*65];   // padded, conflict-free column reads
    __shared__ float s_cnt[KK];
    __shared__ float s_acc[3];        // var, hinge, reg
    __shared__ float s_tot;
    const int t = threadIdx.x;
    if (t == 0) s_tot = 0.f;

    for (int b = 0; b < BB; ++b) {
        if (t < 3) s_acc[t] = 0.f;
        if (t < KK) s_cnt[t] = g_cnt[b*KK + t];
        __syncthreads();
        for (int i = t; i < KK*DDIM; i += blockDim.x) {
            int k = i >> 6, d = i & 63;
            s_mean[k*65 + d] = g_sum[(b*KK + k)*DDIM + d] / fmaxf(s_cnt[k], 1.f);
        }
        __syncthreads();
        if (t < KK) {
            float m2 = 0.f;
#pragma unroll
            for (int d = 0; d < DDIM; ++d) { float m = s_mean[t*65 + d]; m2 = fmaf(m, m, m2); }
            float c = s_cnt[t];
            if (c > 0.f) {
                // sum ||f - mu||^2 = sumsq - cnt*||mu||^2 ; var_per = that / cnt
                atomicAdd(&s_acc[0], (g_sq[b*KK + t] - c*m2) / c);
                atomicAdd(&s_acc[2], sqrtf(m2));
            }
        }
        __syncthreads();
        for (int p = t; p < KK*KK; p += blockDim.x) {
            int i = p >> 5, j = p & 31;
            if (j > i && s_cnt[i] > 0.f && s_cnt[j] > 0.f) {
                float dsq = 0.f;
#pragma unroll
                for (int d = 0; d < DDIM; ++d) {
                    float df = s_mean[i*65 + d] - s_mean[j*65 + d];
                    dsq = fmaf(df, df, dsq);
                }
                float dist = sqrtf(dsq);
                if (dist < 3.0f) {            // 2 * delta_d, delta_d = 1.5
                    float h = 3.0f - dist;
                    atomicAdd(&s_acc[1], h*h);
                }
            }
        }
        __syncthreads();
        if (t == 0) {
            float ncl = 0.f;
            for (int k = 0; k < KK; ++k) ncl += (s_cnt[k] > 0.f) ? 1.f : 0.f;
            float dist_loss = s_acc[1] / fmaxf(ncl - 1.f, 1.f);
            s_tot += (s_acc[0] + dist_loss + 0.001f * s_acc[2]) / fmaxf(ncl, 1.f);
        }
        __syncthreads();
    }
    if (t == 0) out[0] = s_tot / (float)(BB + 1);
}

extern "C" void kernel_launch(void* const* d_in, const int* in_sizes, int n_in,
                              void* d_out, int out_size) {
    const float* feats  = (const float*)d_in[0];
    const int*   labels = (const int*)d_in[1];
    float*       out    = (float*)d_out;

    const int smem_bytes = KK*T*6*(int)sizeof(float);   // 196608
    cudaFuncSetAttribute(accum_kernel, cudaFuncAttributeMaxDynamicSharedMemorySize,
                         smem_bytes);

    zero_kernel<<<32, 256>>>();
    // 8 accum launches (image x half-of-quads) so ncu's -s 5 lands on accum.
    dim3 grid(NCHUNK, QHALF, 1);
    for (int b = 0; b < BB; ++b)
        for (int qh = 0; qh < 2; ++qh)
            accum_kernel<<<grid, T, smem_bytes>>>(feats, labels, b, qh*QHALF);
    finalize_kernel<<<1, 256>>>(out);
}

// round 7
// speedup vs baseline: 1.3907x; 1.3907x over previous
#include <cuda_runtime.h>

// Problem constants
#define BB 4
#define DDIM 64
#define HW (512*512)
#define KK 32

// Tiling: each block = 4 channels (one quad) x CP pixels of one image.
#define T 256
#define CP 16384
#define NCHUNK (HW/CP)     // 16
#define PPT (CP/T)         // 64 pixels per thread
#define NGRP (PPT/4)       // 16 float4 pixel-groups per thread
#define NB (NGRP/2)        // 8 batches of 2 groups (8 pixels)
#define QG (DDIM/4)        // 16 channel quads

// Global scratch (no allocations allowed)
__device__ float g_sum[BB*KK*DDIM];   // per (b,k,d) feature sums
__device__ float g_sq[BB*KK];         // per (b,k) sum of ||f||^2
__device__ float g_cnt[BB*KK];        // per (b,k) pixel counts

__global__ void zero_kernel() {
    int t = blockIdx.x * blockDim.x + threadIdx.x;
    int n = BB*KK*DDIM;
    for (int i = t; i < n; i += gridDim.x * blockDim.x) g_sum[i] = 0.f;
    if (t < BB*KK) { g_sq[t] = 0.f; g_cnt[t] = 0.f; }
}

// SMEM (dynamic, 196608 B): s4[KK*T] float4 | s_sq[KK*T] | s_cnt[KK*T]
// Column = tid -> conflict-free, race-free (each thread owns its column;
// label stride 4096B == 0 mod 128B so bank pattern is label-independent).
__global__ __launch_bounds__(T, 1) void accum_kernel(
    const float* __restrict__ feats, const int* __restrict__ labels,
    int boff)
{
    extern __shared__ float smem[];
    float4* s4    = (float4*)smem;          // KK*T float4
    float*  s_sq  = smem + KK*T*4;          // KK*T floats
    float*  s_cnt = s_sq + KK*T;            // KK*T floats

    const int t     = threadIdx.x;
    const int chunk = blockIdx.x;
    const int q     = blockIdx.y;           // channel quad
    const int b     = boff + blockIdx.z;
    const bool do_cnt = (q == 0);
    const int lane = t & 31;
    const int w    = t >> 5;

    for (int i = t; i < KK*T; i += T) s4[i] = make_float4(0.f, 0.f, 0.f, 0.f);
    for (int i = t; i < KK*T; i += T) s_sq[i] = 0.f;
    if (do_cnt) for (int i = t; i < KK*T; i += T) s_cnt[i] = 0.f;
    __syncthreads();

    const size_t base = (size_t)(b*DDIM + q*4) * HW + (size_t)chunk * CP;
    const float4* __restrict__ F0 = (const float4*)(feats + base);
    const float4* __restrict__ F1 = (const float4*)(feats + base + HW);
    const float4* __restrict__ F2 = (const float4*)(feats + base + 2*(size_t)HW);
    const float4* __restrict__ F3 = (const float4*)(feats + base + 3*(size_t)HW);
    const int4*   __restrict__ L4 = (const int4*)(labels + (size_t)b * HW + (size_t)chunk * CP);

    // Double-buffered staging: 2 groups x (4 channel-float4 + 1 label-int4).
    // All indices constant-fold after unroll -> register resident
    // (launch_bounds(,1) lets ptxas use the registers).
    float4 c[2][2][4];
    int4   lb[2][2];

#pragma unroll
    for (int g = 0; g < 2; ++g) {
        const int idx = g*T + t;
        lb[0][g] = L4[idx];
        c[0][g][0] = F0[idx]; c[0][g][1] = F1[idx];
        c[0][g][2] = F2[idx]; c[0][g][3] = F3[idx];
    }

#pragma unroll
    for (int bt = 0; bt < NB; ++bt) {
        const int cur = bt & 1, nxt = cur ^ 1;
        if (bt + 1 < NB) {
#pragma unroll
            for (int g = 0; g < 2; ++g) {
                const int idx = ((bt+1)*2 + g)*T + t;
                lb[nxt][g] = L4[idx];
                c[nxt][g][0] = F0[idx]; c[nxt][g][1] = F1[idx];
                c[nxt][g][2] = F2[idx]; c[nxt][g][3] = F3[idx];
            }
        }
#pragma unroll
        for (int g = 0; g < 2; ++g) {
            const float4 v0 = c[cur][g][0], v1 = c[cur][g][1];
            const float4 v2 = c[cur][g][2], v3 = c[cur][g][3];
            const int4   L  = lb[cur][g];
#pragma unroll
            for (int p = 0; p < 4; ++p) {
                const float x = (p==0)?v0.x:(p==1)?v0.y:(p==2)?v0.z:v0.w;
                const float y = (p==0)?v1.x:(p==1)?v1.y:(p==2)?v1.z:v1.w;
                const float z = (p==0)?v2.x:(p==1)?v2.y:(p==2)?v2.z:v2.w;
                const float u = (p==0)?v3.x:(p==1)?v3.y:(p==2)?v3.z:v3.w;
                const int bin = ((p==0)?L.x:(p==1)?L.y:(p==2)?L.z:L.w) & 31;
                const int col = bin*T + t;
                float4 a = s4[col];
                a.x += x; a.y += y; a.z += z; a.w += u;
                s4[col] = a;
                float ss = x*x;
                ss = fmaf(y, y, ss);
                ss = fmaf(z, z, ss);
                ss = fmaf(u, u, ss);
                s_sq[col] += ss;
                if (do_cnt) s_cnt[col] += 1.f;
            }
        }
    }
    __syncthreads();

    // flush: warp w reduces bins 4w..4w+3 across the 256 columns
#pragma unroll
    for (int bbn = 0; bbn < 4; ++bbn) {
        const int bin = w*4 + bbn;
        float4 a = make_float4(0.f, 0.f, 0.f, 0.f);
        float sq = 0.f, cn = 0.f;
#pragma unroll
        for (int j = 0; j < T/32; ++j) {
            const int col = bin*T + j*32 + lane;
            float4 x = s4[col];
            a.x += x.x; a.y += x.y; a.z += x.z; a.w += x.w;
            sq += s_sq[col];
            if (do_cnt) cn += s_cnt[col];
        }
#pragma unroll
        for (int off = 16; off; off >>= 1) {
            a.x += __shfl_xor_sync(0xffffffffu, a.x, off);
            a.y += __shfl_xor_sync(0xffffffffu, a.y, off);
            a.z += __shfl_xor_sync(0xffffffffu, a.z, off);
            a.w += __shfl_xor_sync(0xffffffffu, a.w, off);
            sq  += __shfl_xor_sync(0xffffffffu, sq,  off);
            cn  += __shfl_xor_sync(0xffffffffu, cn,  off);
        }
        if (lane < 4) {
            float val = (lane == 0) ? a.x : (lane == 1) ? a.y : (lane == 2) ? a.z : a.w;
            atomicAdd(&g_sum[(b*KK + bin)*DDIM + q*4 + lane], val);
        }
        if (lane == 4)            atomicAdd(&g_sq[b*KK + bin], sq);
        if (do_cnt && lane == 5)  atomicAdd(&g_cnt[b*KK + bin], cn);
    }
}

__global__ void finalize_kernel(float* __restrict__ out) {
    __shared__ float s_mean[KK*65];
    __shared__ float s_cnt[KK];
    __shared__ float s_acc[3];        // var, hinge, reg
    __shared__ float s_tot;
    const int t = threadIdx.x;
    if (t == 0) s_tot = 0.f;

    for (int b = 0; b < BB; ++b) {
        if (t < 3) s_acc[t] = 0.f;
        if (t < KK) s_cnt[t] = g_cnt[b*KK + t];
        __syncthreads();
        for (int i = t; i < KK*DDIM; i += blockDim.x) {
            int k = i >> 6, d = i & 63;
            s_mean[k*65 + d] = g_sum[(b*KK + k)*DDIM + d] / fmaxf(s_cnt[k], 1.f);
        }
        __syncthreads();
        if (t < KK) {
            float m2 = 0.f;
#pragma unroll
            for (int d = 0; d < DDIM; ++d) { float m = s_mean[t*65 + d]; m2 = fmaf(m, m, m2); }
            float cc = s_cnt[t];
            if (cc > 0.f) {
                atomicAdd(&s_acc[0], (g_sq[b*KK + t] - cc*m2) / cc);
                atomicAdd(&s_acc[2], sqrtf(m2));
            }
        }
        __syncthreads();
        for (int p = t; p < KK*KK; p += blockDim.x) {
            int i = p >> 5, j = p & 31;
            if (j > i && s_cnt[i] > 0.f && s_cnt[j] > 0.f) {
                float dsq = 0.f;
#pragma unroll
                for (int d = 0; d < DDIM; ++d) {
                    float df = s_mean[i*65 + d] - s_mean[j*65 + d];
                    dsq = fmaf(df, df, dsq);
                }
                float dist = sqrtf(dsq);
                if (dist < 3.0f) {            // 2*delta_d, delta_d = 1.5
                    float h = 3.0f - dist;
                    atomicAdd(&s_acc[1], h*h);
                }
            }
        }
        __syncthreads();
        if (t == 0) {
            float ncl = 0.f;
            for (int k = 0; k < KK; ++k) ncl += (s_cnt[k] > 0.f) ? 1.f : 0.f;
            float dist_loss = s_acc[1] / fmaxf(ncl - 1.f, 1.f);
            s_tot += (s_acc[0] + dist_loss + 0.001f * s_acc[2]) / fmaxf(ncl, 1.f);
        }
        __syncthreads();
    }
    if (t == 0) out[0] = s_tot / (float)(BB + 1);
}

extern "C" void kernel_launch(void* const* d_in, const int* in_sizes, int n_in,
                              void* d_out, int out_size) {
    const float* feats  = (const float*)d_in[0];
    const int*   labels = (const int*)d_in[1];
    float*       out    = (float*)d_out;

    const int smem_bytes = KK*T*6*(int)sizeof(float);   // 196608
    cudaFuncSetAttribute(accum_kernel, cudaFuncAttributeMaxDynamicSharedMemorySize,
                         smem_bytes);

    zero_kernel<<<32, 256>>>();
    // 2 accum launches (b in {0,1} then {2,3}); 4 launches/iter keeps ncu -s 5 on accum.
    dim3 grid(NCHUNK, QG, 2);
    accum_kernel<<<grid, T, smem_bytes>>>(feats, labels, 0);
    accum_kernel<<<grid, T, smem_bytes>>>(feats, labels, 2);
    finalize_kernel<<<1, 256>>>(out);
}

// round 10
// speedup vs baseline: 2.5135x; 1.8074x over previous
#include <cuda_runtime.h>

// Problem constants
#define BB 4
#define DDIM 64
#define HW (512*512)
#define KK 32

// Accum tiling: each block = 4 channels (one quad) x CP pixels of one image.
#define T 256
#define CP 16384
#define NCHUNK (HW/CP)     // 16
#define NB 8               // batches of 2 float4-groups (8 pixels) per thread
#define QG (DDIM/4)        // 16 channel quads

// Global scratch (no allocations allowed)
__device__ float g_sum[BB*KK*DDIM];   // per (b,k,d) feature sums
__device__ float g_sq[BB*KK];         // per (b,k) sum of ||f||^2
__device__ float g_cnt[BB*KK];        // per (b,k) pixel counts
__device__ float g_loss[BB];          // per-image losses

__global__ void zero_kernel() {
    int t = blockIdx.x * blockDim.x + threadIdx.x;
    int n = BB*KK*DDIM;
    for (int i = t; i < n; i += gridDim.x * blockDim.x) g_sum[i] = 0.f;
    if (t < BB*KK) { g_sq[t] = 0.f; g_cnt[t] = 0.f; }
}

// Label histogram: grid (64 chunks, BB images), 256 thr, 4096 px/block.
__global__ __launch_bounds__(T) void count_kernel(const int* __restrict__ labels) {
    __shared__ float s_cnt[KK*T];
    const int t = threadIdx.x, lane = t & 31, w = t >> 5;
    const int b = blockIdx.y;
    for (int i = t; i < KK*T; i += T) s_cnt[i] = 0.f;
    __syncthreads();
    const int4* L4 = (const int4*)(labels + (size_t)b * HW + (size_t)blockIdx.x * 4096);
#pragma unroll
    for (int g = 0; g < 4; ++g) {
        int4 L = L4[g*T + t];
        s_cnt[(L.x & 31)*T + t] += 1.f;
        s_cnt[(L.y & 31)*T + t] += 1.f;
        s_cnt[(L.z & 31)*T + t] += 1.f;
        s_cnt[(L.w & 31)*T + t] += 1.f;
    }
    __syncthreads();
#pragma unroll
    for (int bbn = 0; bbn < 4; ++bbn) {
        const int bin = w*4 + bbn;
        float c = 0.f;
#pragma unroll
        for (int j = 0; j < T/32; ++j) c += s_cnt[bin*T + j*32 + lane];
#pragma unroll
        for (int off = 16; off; off >>= 1) c += __shfl_xor_sync(0xffffffffu, c, off);
        if (lane == 0) atomicAdd(&g_cnt[b*KK + bin], c);
    }
}

// SMEM (dynamic, 163840 B): s4[KK*T] float4 | s_sq[KK*T] float
// Column = tid -> conflict-free, race-free (each thread owns its column).
__global__ __launch_bounds__(T, 1) void accum_kernel(
    const float* __restrict__ feats, const int* __restrict__ labels)
{
    extern __shared__ float smem[];
    float4* s4   = (float4*)smem;           // KK*T float4
    float*  s_sq = smem + KK*T*4;           // KK*T floats

    const int t     = threadIdx.x;
    const int chunk = blockIdx.x;
    const int q     = blockIdx.y;           // channel quad
    const int b     = blockIdx.z;
    const int lane = t & 31;
    const int w    = t >> 5;

    for (int i = t; i < KK*T; i += T) s4[i] = make_float4(0.f, 0.f, 0.f, 0.f);
    for (int i = t; i < KK*T; i += T) s_sq[i] = 0.f;
    __syncthreads();

    const size_t base = (size_t)(b*DDIM + q*4) * HW + (size_t)chunk * CP;
    const float4* __restrict__ F0 = (const float4*)(feats + base);
    const float4* __restrict__ F1 = (const float4*)(feats + base + HW);
    const float4* __restrict__ F2 = (const float4*)(feats + base + 2*(size_t)HW);
    const float4* __restrict__ F3 = (const float4*)(feats + base + 3*(size_t)HW);
    const int4*   __restrict__ L4 = (const int4*)(labels + (size_t)b * HW + (size_t)chunk * CP);

    // Double-buffered staging: 2 groups x (4 channel-float4 + 1 label-int4).
    float4 c[2][2][4];
    int4   lb[2][2];

#pragma unroll
    for (int g = 0; g < 2; ++g) {
        const int idx = g*T + t;
        lb[0][g] = L4[idx];
        c[0][g][0] = F0[idx]; c[0][g][1] = F1[idx];
        c[0][g][2] = F2[idx]; c[0][g][3] = F3[idx];
    }

#pragma unroll
    for (int bt = 0; bt < NB; ++bt) {
        const int cur = bt & 1, nxt = cur ^ 1;
        if (bt + 1 < NB) {
#pragma unroll
            for (int g = 0; g < 2; ++g) {
                const int idx = ((bt+1)*2 + g)*T + t;
                lb[nxt][g] = L4[idx];
                c[nxt][g][0] = F0[idx]; c[nxt][g][1] = F1[idx];
                c[nxt][g][2] = F2[idx]; c[nxt][g][3] = F3[idx];
            }
        }
#pragma unroll
        for (int g = 0; g < 2; ++g) {
            const float4 v0 = c[cur][g][0], v1 = c[cur][g][1];
            const float4 v2 = c[cur][g][2], v3 = c[cur][g][3];
            const int4   L  = lb[cur][g];
#pragma unroll
            for (int p = 0; p < 4; ++p) {
                const float x = (p==0)?v0.x:(p==1)?v0.y:(p==2)?v0.z:v0.w;
                const float y = (p==0)?v1.x:(p==1)?v1.y:(p==2)?v1.z:v1.w;
                const float z = (p==0)?v2.x:(p==1)?v2.y:(p==2)?v2.z:v2.w;
                const float u = (p==0)?v3.x:(p==1)?v3.y:(p==2)?v3.z:v3.w;
                const int bin = ((p==0)?L.x:(p==1)?L.y:(p==2)?L.z:L.w) & 31;
                const int col = bin*T + t;
                float4 a = s4[col];
                a.x += x; a.y += y; a.z += z; a.w += u;
                s4[col] = a;
                float ss = x*x;
                ss = fmaf(y, y, ss);
                ss = fmaf(z, z, ss);
                ss = fmaf(u, u, ss);
                s_sq[col] += ss;
            }
        }
    }
    __syncthreads();

    // flush: warp w reduces bins 4w..4w+3 across the 256 columns
#pragma unroll
    for (int bbn = 0; bbn < 4; ++bbn) {
        const int bin = w*4 + bbn;
        float4 a = make_float4(0.f, 0.f, 0.f, 0.f);
        float sq = 0.f;
#pragma unroll
        for (int j = 0; j < T/32; ++j) {
            const int col = bin*T + j*32 + lane;
            float4 x = s4[col];
            a.x += x.x; a.y += x.y; a.z += x.z; a.w += x.w;
            sq += s_sq[col];
        }
#pragma unroll
        for (int off = 16; off; off >>= 1) {
            a.x += __shfl_xor_sync(0xffffffffu, a.x, off);
            a.y += __shfl_xor_sync(0xffffffffu, a.y, off);
            a.z += __shfl_xor_sync(0xffffffffu, a.z, off);
            a.w += __shfl_xor_sync(0xffffffffu, a.w, off);
            sq  += __shfl_xor_sync(0xffffffffu, sq,  off);
        }
        if (lane < 4) {
            float val = (lane == 0) ? a.x : (lane == 1) ? a.y : (lane == 2) ? a.z : a.w;
            atomicAdd(&g_sum[(b*KK + bin)*DDIM + q*4 + lane], val);
        }
        if (lane == 4) atomicAdd(&g_sq[b*KK + bin], sq);
    }
}

// One block per image, 1024 threads: 1 (i,j) pair per thread.
__global__ __launch_bounds__(1024) void finalize_kernel() {
    __shared__ float s_mean[KK*65];   // padded, conflict-free column reads
    __shared__ float s_cnt[KK];
    __shared__ float s_acc[3];        // var, hinge, reg
    const int t = threadIdx.x;
    const int b = blockIdx.x;
    const int w = t >> 5, lane = t & 31;

    if (t < 3) s_acc[t] = 0.f;
    if (t < KK) s_cnt[t] = g_cnt[b*KK + t];
    __syncthreads();

    // means: 2048 values, 2 per thread
    for (int i = t; i < KK*DDIM; i += 1024) {
        int k = i >> 6, d = i & 63;
        s_mean[k*65 + d] = g_sum[(b*KK + k)*DDIM + d] / fmaxf(s_cnt[k], 1.f);
    }
    __syncthreads();

    // m2 / var / reg: warp w handles cluster k = w
    {
        float m0 = s_mean[w*65 + lane];
        float m1 = s_mean[w*65 + lane + 32];
        float p = fmaf(m0, m0, m1*m1);
#pragma unroll
        for (int off = 16; off; off >>= 1) p += __shfl_xor_sync(0xffffffffu, p, off);
        if (lane == 0) {
            float cc = s_cnt[w];
            if (cc > 0.f) {
                // sum ||f - mu||^2 = sumsq - cnt*||mu||^2 ; var_per = that / cnt
                atomicAdd(&s_acc[0], (g_sq[b*KK + w] - cc*p) / cc);
                atomicAdd(&s_acc[2], sqrtf(p));
            }
        }
    }

    // pairwise hinge: i = w (warp, broadcast row), j = lane (conflict-free row)
    if (lane > w && s_cnt[w] > 0.f && s_cnt[lane] > 0.f) {
        float dsq = 0.f;
#pragma unroll
        for (int d = 0; d < DDIM; ++d) {
            float df = s_mean[w*65 + d] - s_mean[lane*65 + d];
            dsq = fmaf(df, df, dsq);
        }
        float dist = sqrtf(dsq);
        if (dist < 3.0f) {                    // 2*delta_d, delta_d = 1.5
            float h = 3.0f - dist;
            atomicAdd(&s_acc[1], h*h);
        }
    }
    __syncthreads();

    if (t == 0) {
        float ncl = 0.f;
        for (int k = 0; k < KK; ++k) ncl += (s_cnt[k] > 0.f) ? 1.f : 0.f;
        float dist_loss = s_acc[1] / fmaxf(ncl - 1.f, 1.f);
        g_loss[b] = (s_acc[0] + dist_loss + 0.001f * s_acc[2]) / fmaxf(ncl, 1.f);
    }
}

__global__ void combine_kernel(float* __restrict__ out) {
    if (threadIdx.x == 0)
        out[0] = (g_loss[0] + g_loss[1] + g_loss[2] + g_loss[3]) / (float)(BB + 1);
}

extern "C" void kernel_launch(void* const* d_in, const int* in_sizes, int n_in,
                              void* d_out, int out_size) {
    const float* feats  = (const float*)d_in[0];
    const int*   labels = (const int*)d_in[1];
    float*       out    = (float*)d_out;

    const int smem_bytes = KK*T*5*(int)sizeof(float);   // 163840
    cudaFuncSetAttribute(accum_kernel, cudaFuncAttributeMaxDynamicSharedMemorySize,
                         smem_bytes);

    zero_kernel<<<32, 256>>>();
    count_kernel<<<dim3(64, BB), T>>>(labels);
    accum_kernel<<<dim3(NCHUNK, QG, BB), T, smem_bytes>>>(feats, labels);
    finalize_kernel<<<BB, 1024>>>();
    combine_kernel<<<1, 32>>>(out);
}

// round 11
// speedup vs baseline: 2.6463x; 1.0528x over previous
#include <cuda_runtime.h>

// Problem constants
#define BB 4
#define DDIM 64
#define HW (512*512)
#define KK 32

// Accum tiling: each block = 2 channels (one pair) x CP pixels of one image.
#define T 256
#define CP 16384
#define NCHUNK (HW/CP)     // 16
#define NB 8               // batches of 2 float4-groups (8 pixels) per thread
#define NQ (DDIM/2)        // 32 channel pairs

// Global scratch (no allocations; all fully overwritten each call -> no zeroing)
__device__ float g_sum_part[BB*NQ*KK*2*NCHUNK];  // [(b,q,k)][ch][chunk]
__device__ float g_sq_part[BB*KK*NQ*NCHUNK];     // [(b,k)][q][chunk]
__device__ float g_cnt_part[BB*KK*64];           // [(b,k)][chunk64]
__device__ unsigned char g_lab8[BB*HW];          // packed labels (bytes)
__device__ float g_loss[BB];                     // per-image losses

// Label histogram + byte-pack: grid (64, BB), 256 thr, 4096 px/block.
__global__ __launch_bounds__(T) void count_kernel(const int* __restrict__ labels) {
    __shared__ float s_cnt[KK*T];
    const int t = threadIdx.x, lane = t & 31, w = t >> 5;
    const int b = blockIdx.y;
    for (int i = t; i < KK*T; i += T) s_cnt[i] = 0.f;
    __syncthreads();
    const int4* L4 = (const int4*)(labels + (size_t)b * HW + (size_t)blockIdx.x * 4096);
    uchar4* P4 = (uchar4*)g_lab8 + ((size_t)b * HW >> 2) + (size_t)blockIdx.x * 1024;
#pragma unroll
    for (int g = 0; g < 4; ++g) {
        int4 L = L4[g*T + t];
        int x = L.x & 31, y = L.y & 31, z = L.z & 31, u = L.w & 31;
        s_cnt[x*T + t] += 1.f;
        s_cnt[y*T + t] += 1.f;
        s_cnt[z*T + t] += 1.f;
        s_cnt[u*T + t] += 1.f;
        P4[g*T + t] = make_uchar4((unsigned char)x, (unsigned char)y,
                                  (unsigned char)z, (unsigned char)u);
    }
    __syncthreads();
#pragma unroll
    for (int bbn = 0; bbn < 4; ++bbn) {
        const int bin = w*4 + bbn;
        float c = 0.f;
#pragma unroll
        for (int j = 0; j < T/32; ++j) c += s_cnt[bin*T + j*32 + lane];
#pragma unroll
        for (int off = 16; off; off >>= 1) c += __shfl_xor_sync(0xffffffffu, c, off);
        if (lane == 0) g_cnt_part[(b*KK + bin)*64 + blockIdx.x] = c;
    }
}

// SMEM (dynamic, 98304 B): s2[KK*T] float2 | s_sq[KK*T] float  -> 2 blocks/SM.
// Column = tid -> conflict-free, race-free (each thread owns its column).
__global__ __launch_bounds__(T, 2) void accum_kernel(const float* __restrict__ feats)
{
    extern __shared__ float smem[];
    float2* s2   = (float2*)smem;           // KK*T float2
    float*  s_sq = smem + KK*T*2;           // KK*T floats

    const int t     = threadIdx.x;
    const int chunk = blockIdx.x;
    const int q     = blockIdx.y;           // channel pair
    const int b     = blockIdx.z;
    const int lane = t & 31;
    const int w    = t >> 5;

    for (int i = t; i < KK*T; i += T) { s2[i] = make_float2(0.f, 0.f); s_sq[i] = 0.f; }
    __syncthreads();

    const size_t base = (size_t)(b*DDIM + q*2) * HW + (size_t)chunk * CP;
    const float4* __restrict__ F0 = (const float4*)(feats + base);
    const float4* __restrict__ F1 = (const float4*)(feats + base + HW);
    const uchar4* __restrict__ LB = (const uchar4*)g_lab8
                                  + (((size_t)b * HW + (size_t)chunk * CP) >> 2);

    // Double-buffered register staging: 2 groups x (2 channel-float4 + labels).
    float4 c[2][2][2];
    uchar4 lb[2][2];

#pragma unroll
    for (int g = 0; g < 2; ++g) {
        const int idx = g*T + t;
        lb[0][g] = LB[idx];
        c[0][g][0] = F0[idx]; c[0][g][1] = F1[idx];
    }

#pragma unroll
    for (int bt = 0; bt < NB; ++bt) {
        const int cur = bt & 1, nxt = cur ^ 1;
        if (bt + 1 < NB) {
#pragma unroll
            for (int g = 0; g < 2; ++g) {
                const int idx = ((bt+1)*2 + g)*T + t;
                lb[nxt][g] = LB[idx];
                c[nxt][g][0] = F0[idx]; c[nxt][g][1] = F1[idx];
            }
        }
#pragma unroll
        for (int g = 0; g < 2; ++g) {
            const float4 v0 = c[cur][g][0], v1 = c[cur][g][1];
            const uchar4 L  = lb[cur][g];
#pragma unroll
            for (int p = 0; p < 4; ++p) {
                const float x = (p==0)?v0.x:(p==1)?v0.y:(p==2)?v0.z:v0.w;
                const float y = (p==0)?v1.x:(p==1)?v1.y:(p==2)?v1.z:v1.w;
                const int bin = (p==0)?L.x:(p==1)?L.y:(p==2)?L.z:L.w;
                const int col = bin*T + t;
                float2 a = s2[col];
                a.x += x; a.y += y;
                s2[col] = a;
                s_sq[col] = fmaf(x, x, fmaf(y, y, s_sq[col]));
            }
        }
    }
    __syncthreads();

    // flush: warp w reduces bins 4w..4w+3; non-atomic partial writes
#pragma unroll
    for (int bbn = 0; bbn < 4; ++bbn) {
        const int bin = w*4 + bbn;
        float ax = 0.f, ay = 0.f, sq = 0.f;
#pragma unroll
        for (int j = 0; j < T/32; ++j) {
            const int col = bin*T + j*32 + lane;
            float2 v = s2[col];
            ax += v.x; ay += v.y;
            sq += s_sq[col];
        }
#pragma unroll
        for (int off = 16; off; off >>= 1) {
            ax += __shfl_xor_sync(0xffffffffu, ax, off);
            ay += __shfl_xor_sync(0xffffffffu, ay, off);
            sq += __shfl_xor_sync(0xffffffffu, sq, off);
        }
        if (lane == 0) {
            const int sbase = ((b*NQ + q)*KK + bin)*(2*NCHUNK);
            g_sum_part[sbase + chunk]          = ax;
            g_sum_part[sbase + NCHUNK + chunk] = ay;
            g_sq_part[((b*KK + bin)*NQ + q)*NCHUNK + chunk] = sq;
        }
    }
}

// Grid padded to 148 blocks to defeat the low-grid issue throttle; blocks >= BB exit.
__global__ __launch_bounds__(1024) void finalize_kernel() {
    const int b = blockIdx.x;
    if (b >= BB) return;
    __shared__ float s_mean[KK*65];   // padded, conflict-free column reads
    __shared__ float s_cnt[KK];
    __shared__ float s_acc[3];        // var, hinge, reg
    const int t = threadIdx.x;
    const int w = t >> 5, lane = t & 31;

    if (t < 3) s_acc[t] = 0.f;

    // counts: warp w reduces bin w's 64 chunk-partials
    {
        const float* p = &g_cnt_part[(b*KK + w)*64];
        float cc = p[lane] + p[lane + 32];
#pragma unroll
        for (int off = 16; off; off >>= 1) cc += __shfl_xor_sync(0xffffffffu, cc, off);
        if (lane == 0) s_cnt[w] = cc;
    }
    __syncthreads();

    // means: 2048 (k,d) entries, 2 per thread, 16 chunk-partials each (4x float4)
    for (int i = t; i < KK*DDIM; i += 1024) {
        const int k = i >> 6, d = i & 63, q = d >> 1, ch = d & 1;
        const float4* p4 = (const float4*)&g_sum_part[((b*NQ + q)*KK + k)*(2*NCHUNK) + ch*NCHUNK];
        float4 a = p4[0], b4 = p4[1], c4 = p4[2], d4 = p4[3];
        float s = ((a.x + a.y) + (a.z + a.w)) + ((b4.x + b4.y) + (b4.z + b4.w))
                + ((c4.x + c4.y) + (c4.z + c4.w)) + ((d4.x + d4.y) + (d4.z + d4.w));
        s_mean[k*65 + d] = s / fmaxf(s_cnt[k], 1.f);
    }
    __syncthreads();

    // per-cluster: m2 + sumsq partial reduce (warp w = cluster w)
    {
        float m0 = s_mean[w*65 + lane];
        float m1 = s_mean[w*65 + lane + 32];
        float p = fmaf(m0, m0, m1*m1);
        const float4* q4 = (const float4*)&g_sq_part[(b*KK + w)*NQ*NCHUNK];  // 512 floats
        float sq = 0.f;
#pragma unroll
        for (int j = 0; j < 4; ++j) {
            float4 v = q4[lane + 32*j];
            sq += (v.x + v.y) + (v.z + v.w);
        }
#pragma unroll
        for (int off = 16; off; off >>= 1) {
            p  += __shfl_xor_sync(0xffffffffu, p,  off);
            sq += __shfl_xor_sync(0xffffffffu, sq, off);
        }
        if (lane == 0) {
            float cc = s_cnt[w];
            if (cc > 0.f) {
                // sum ||f - mu||^2 = sumsq - cnt*||mu||^2 ; var_per = that / cnt
                atomicAdd(&s_acc[0], (sq - cc*p) / cc);
                atomicAdd(&s_acc[2], sqrtf(p));
            }
        }
    }

    // pairwise hinge: i = w (broadcast row), j = lane (conflict-free row)
    if (lane > w && s_cnt[w] > 0.f && s_cnt[lane] > 0.f) {
        float dsq = 0.f;
#pragma unroll
        for (int d = 0; d < DDIM; ++d) {
            float df = s_mean[w*65 + d] - s_mean[lane*65 + d];
            dsq = fmaf(df, df, dsq);
        }
        float dist = sqrtf(dsq);
        if (dist < 3.0f) {                    // 2*delta_d, delta_d = 1.5
            float h = 3.0f - dist;
            atomicAdd(&s_acc[1], h*h);
        }
    }
    __syncthreads();

    if (t == 0) {
        float ncl = 0.f;
        for (int k = 0; k < KK; ++k) ncl += (s_cnt[k] > 0.f) ? 1.f : 0.f;
        float dist_loss = s_acc[1] / fmaxf(ncl - 1.f, 1.f);
        g_loss[b] = (s_acc[0] + dist_loss + 0.001f * s_acc[2]) / fmaxf(ncl, 1.f);
    }
}

__global__ void combine_kernel(float* __restrict__ out) {
    if (threadIdx.x == 0)
        out[0] = (g_loss[0] + g_loss[1] + g_loss[2] + g_loss[3]) / (float)(BB + 1);
}

extern "C" void kernel_launch(void* const* d_in, const int* in_sizes, int n_in,
                              void* d_out, int out_size) {
    const float* feats  = (const float*)d_in[0];
    const int*   labels = (const int*)d_in[1];
    float*       out    = (float*)d_out;

    const int smem_bytes = KK*T*3*(int)sizeof(float);   // 98304 -> 2 blocks/SM
    cudaFuncSetAttribute(accum_kernel, cudaFuncAttributeMaxDynamicSharedMemorySize,
                         smem_bytes);

    count_kernel<<<dim3(64, BB), T>>>(labels);
    accum_kernel<<<dim3(NCHUNK, NQ, BB), T, smem_bytes>>>(feats);
    finalize_kernel<<<148, 1024>>>();
    combine_kernel<<<1, 32>>>(out);
}